// round 1
// baseline (speedup 1.0000x reference)
#include <cuda_runtime.h>

// ---------------------------------------------------------------------------
// Scratch (static __device__ arrays; no allocation allowed)
// bufA: max 64^3*64 floats = 64MB ; bufB: max 32^3*128 = 16MB
// ---------------------------------------------------------------------------
__device__ float g_bufA[16777216];
__device__ float g_bufB[4194304];

// ---------------------------------------------------------------------------
// f32x2 packed helpers (Blackwell: fma.rn.f32x2 doubles fp32 FMA issue rate)
// ---------------------------------------------------------------------------
__device__ __forceinline__ unsigned long long pack2(float x, float y){
  unsigned long long r;
  asm("mov.b64 %0, {%1, %2};" : "=l"(r) : "f"(x), "f"(y));
  return r;
}
__device__ __forceinline__ void unpack2(unsigned long long v, float& x, float& y){
  asm("mov.b64 {%0, %1}, %2;" : "=f"(x), "=f"(y) : "l"(v));
}
__device__ __forceinline__ void ffma2(unsigned long long& acc,
                                      unsigned long long a, unsigned long long b){
  asm("fma.rn.f32x2 %0, %1, %2, %0;" : "+l"(acc) : "l"(a), "l"(b));
}

// ---------------------------------------------------------------------------
// Generic transposed-conv as implicit GEMM over (tap, cin) with parity
// decomposition for stride 2 (blockIdx.z = parity class; zero wasted taps).
//
//   out[od,oh,ow,co] = bias[co] + sum_{kd,kh,kw,ci} x[id,ih,iw,ci]*w[kd,kh,kw,ci,co]
//   id = (od + kd - pad)/s  valid iff divisible & in range
//   s=2, pad=2:  od=2m   -> kd in {0,2}, id in {m-1, m}
//                od=2m+1 -> kd = 1,      id = m
//   s=1, pad=1:  id = od + kd - 1
//
// Tiling: BM voxels x 64 couts, BK=16 cin chunk, 256 threads.
// Each thread: TM voxels x 4 couts, accumulated as f32x2 voxel-pairs.
// ---------------------------------------------------------------------------
template<int BM, int TM>
__global__ __launch_bounds__(256) void deconv_gemm(
    const float* __restrict__ x, const float* __restrict__ w,
    const float* __restrict__ bias, float* __restrict__ out,
    int inD, int inH, int inW, int Cin,
    int outD, int outH, int outW, int Cout,
    int stride, int relu)
{
  constexpr int BN = 64;
  constexpr int BK = 16;
  constexpr int NP = TM / 2;   // voxel pairs per thread

  __shared__ float As[BK][BM];
  __shared__ float Bs[BK][BN];
  __shared__ int   offs[BM];

  const int tid = threadIdx.x;
  const int pz = blockIdx.z;
  const int pd = (pz >> 2) & 1, ph = (pz >> 1) & 1, pw = pz & 1;
  const int rD = outD / stride, rH = outH / stride, rW = outW / stride;
  const int nb = blockIdx.y * BN;
  const int vbase = blockIdx.x * BM;

  // reduced-grid coords of this thread's assigned tile voxel (tid < BM)
  int md = 0, mh = 0, mw = 0;
  if (tid < BM) {
    int rv = vbase + tid;
    mw = rv % rW; int t = rv / rW; mh = t % rH; md = t / rH;
  }

  // per-dimension tap lists: (kernel index k, input delta dd)
  int nkd, kdL[3], ddL[3];
  int nkh, khL[3], dhL[3];
  int nkw, kwL[3], dwL[3];
  auto mk = [&](int p, int& n, int* kL, int* dL){
    if (stride == 1){ n = 3; kL[0]=0; kL[1]=1; kL[2]=2; dL[0]=-1; dL[1]=0; dL[2]=1; }
    else if (p == 0){ n = 2; kL[0]=0; kL[1]=2; dL[0]=-1; dL[1]=0; }
    else            { n = 1; kL[0]=1; dL[0]=0; }
  };
  mk(pd, nkd, kdL, ddL);
  mk(ph, nkh, khL, dhL);
  mk(pw, nkw, kwL, dwL);

  const int mg = tid >> 4, ng = tid & 15;
  const int m0 = mg * TM, n0 = ng * 4;

  unsigned long long acc[NP][4];
  #pragma unroll
  for (int i = 0; i < NP; i++)
    #pragma unroll
    for (int j = 0; j < 4; j++) acc[i][j] = 0ull;

  for (int ia = 0; ia < nkd; ia++)
  for (int ib = 0; ib < nkh; ib++)
  for (int ic = 0; ic < nkw; ic++){
    const int tap = (kdL[ia]*3 + khL[ib])*3 + kwL[ic];
    const float* wt = w + (size_t)tap * Cin * Cout + nb;

    __syncthreads();                       // all readers of offs/As/Bs done
    if (tid < BM){
      int id = md + ddL[ia];
      int ih = mh + dhL[ib];
      int iw = mw + dwL[ic];
      bool v = (unsigned)id < (unsigned)inD &&
               (unsigned)ih < (unsigned)inH &&
               (unsigned)iw < (unsigned)inW;
      offs[tid] = v ? ((id*inH + ih)*inW + iw) * Cin : -1;
    }

    for (int c0 = 0; c0 < Cin; c0 += BK){
      __syncthreads();                     // offs visible; prev compute done
      // ---- A tile: BM voxels x BK cins (transposed into As[k][v]) ----
      for (int idx = tid; idx < BM*4; idx += 256){
        int v = idx >> 2, c4 = (idx & 3) * 4;
        int o = offs[v];
        float4 val = make_float4(0.f, 0.f, 0.f, 0.f);
        if (o >= 0) val = *(const float4*)(x + o + c0 + c4);
        As[c4+0][v] = val.x; As[c4+1][v] = val.y;
        As[c4+2][v] = val.z; As[c4+3][v] = val.w;
      }
      // ---- B tile: BK cins x 64 couts ----
      {
        int r = tid >> 4, col = (tid & 15) * 4;
        float4 bv = *(const float4*)(wt + (size_t)(c0 + r) * Cout + col);
        *(float4*)&Bs[r][col] = bv;
      }
      __syncthreads();
      // ---- FFMA2 inner product ----
      #pragma unroll
      for (int kk = 0; kk < BK; kk++){
        const unsigned long long* a64 = (const unsigned long long*)&As[kk][m0];
        float4 bv = *(const float4*)&Bs[kk][n0];
        unsigned long long bp0 = pack2(bv.x, bv.x);
        unsigned long long bp1 = pack2(bv.y, bv.y);
        unsigned long long bp2 = pack2(bv.z, bv.z);
        unsigned long long bp3 = pack2(bv.w, bv.w);
        #pragma unroll
        for (int i = 0; i < NP; i++){
          unsigned long long av = a64[i];
          ffma2(acc[i][0], av, bp0);
          ffma2(acc[i][1], av, bp1);
          ffma2(acc[i][2], av, bp2);
          ffma2(acc[i][3], av, bp3);
        }
      }
    }
  }

  // ---- epilogue: bias (+ relu), scatter to strided output voxels ----
  float4 b4 = *(const float4*)&bias[nb + n0];
  #pragma unroll
  for (int i = 0; i < NP; i++){
    float r0[4], r1[4];
    #pragma unroll
    for (int j = 0; j < 4; j++) unpack2(acc[i][j], r0[j], r1[j]);
    #pragma unroll
    for (int h = 0; h < 2; h++){
      float* rr = h ? r1 : r0;
      int rv = vbase + m0 + 2*i + h;
      int vw = rv % rW; int t = rv / rW; int vh = t % rH; int vd = t / rH;
      int od = vd*stride + pd, oh = vh*stride + ph, ow = vw*stride + pw;
      size_t oo = (size_t)((od*outH + oh)*outW + ow) * Cout + nb + n0;
      float4 res;
      res.x = rr[0] + b4.x; res.y = rr[1] + b4.y;
      res.z = rr[2] + b4.z; res.w = rr[3] + b4.w;
      if (relu){
        res.x = fmaxf(res.x, 0.f); res.y = fmaxf(res.y, 0.f);
        res.z = fmaxf(res.z, 0.f); res.w = fmaxf(res.w, 0.f);
      }
      *(float4*)&out[oo] = res;
    }
  }
}

// ---------------------------------------------------------------------------
// Final layer: 64^3, cin=64 -> cout=3, stride 1. Warp-cooperative dot:
// lanes split cin (coalesced x loads), weights (27*64*3 = 20KB) in SMEM,
// butterfly reduce, lane 0 writes 3 floats per voxel.
// One block per (od,oh) row; 8 warps x 8 iters cover ow=0..63.
// ---------------------------------------------------------------------------
__global__ __launch_bounds__(256) void deconv_last(
    const float* __restrict__ x, const float* __restrict__ w,
    const float* __restrict__ bias, float* __restrict__ out)
{
  __shared__ float ws[5184];
  __shared__ float bs[3];
  const int tid = threadIdx.x;
  for (int i = tid; i < 5184; i += 256) ws[i] = w[i];
  if (tid < 3) bs[tid] = bias[tid];
  __syncthreads();

  const int row = blockIdx.x;          // od*64 + oh
  const int od = row >> 6, oh = row & 63;
  const int warp = tid >> 5, lane = tid & 31;
  const int w3 = lane * 3;

  for (int it = 0; it < 8; ++it){
    const int ow = warp * 8 + it;
    float a0 = 0.f, a1 = 0.f, a2 = 0.f;
    #pragma unroll
    for (int kd = 0; kd < 3; kd++){
      int id = od + kd - 1;
      if ((unsigned)id >= 64u) continue;
      #pragma unroll
      for (int kh = 0; kh < 3; kh++){
        int ih = oh + kh - 1;
        if ((unsigned)ih >= 64u) continue;
        const float* xr = x + (size_t)((id*64 + ih)*64) * 64;
        const float* wr = ws + (kd*3 + kh) * 3 * 192;
        #pragma unroll
        for (int kw = 0; kw < 3; kw++){
          int iw = ow + kw - 1;
          if ((unsigned)iw >= 64u) continue;
          const float* xp = xr + iw * 64;
          float x0 = xp[lane], x1 = xp[lane + 32];
          const float* wp = wr + kw * 192;
          a0 += x0 * wp[w3+0] + x1 * wp[w3+96];
          a1 += x0 * wp[w3+1] + x1 * wp[w3+97];
          a2 += x0 * wp[w3+2] + x1 * wp[w3+98];
        }
      }
    }
    #pragma unroll
    for (int s = 16; s > 0; s >>= 1){
      a0 += __shfl_xor_sync(0xffffffffu, a0, s);
      a1 += __shfl_xor_sync(0xffffffffu, a1, s);
      a2 += __shfl_xor_sync(0xffffffffu, a2, s);
    }
    if (lane == 0){
      float* op = out + ((size_t)row * 64 + ow) * 3;
      op[0] = a0 + bs[0];
      op[1] = a1 + bs[1];
      op[2] = a2 + bs[2];
    }
  }
}

// ---------------------------------------------------------------------------
// kernel_launch: 6 back-to-back kernels, ping-pong through static scratch.
// inputs: x, w0,b0, w00,b00, w1,b1, w10,b10, w2,b2, w20,b20
// ---------------------------------------------------------------------------
extern "C" void kernel_launch(void* const* d_in, const int* in_sizes, int n_in,
                              void* d_out, int out_size)
{
  (void)in_sizes; (void)n_in; (void)out_size;
  const float* x   = (const float*)d_in[0];
  const float* w0  = (const float*)d_in[1];
  const float* b0  = (const float*)d_in[2];
  const float* w00 = (const float*)d_in[3];
  const float* b00 = (const float*)d_in[4];
  const float* w1  = (const float*)d_in[5];
  const float* b1  = (const float*)d_in[6];
  const float* w10 = (const float*)d_in[7];
  const float* b10 = (const float*)d_in[8];
  const float* w2  = (const float*)d_in[9];
  const float* b2  = (const float*)d_in[10];
  const float* w20 = (const float*)d_in[11];
  const float* b20 = (const float*)d_in[12];
  float* out = (float*)d_out;

  float *bufA = nullptr, *bufB = nullptr;
  cudaGetSymbolAddress((void**)&bufA, g_bufA);
  cudaGetSymbolAddress((void**)&bufB, g_bufB);

  // L1: deconv0, stride 2: x(8^3,128) -> bufA(16^3,128)
  {
    dim3 g(512/32, 128/64, 8);
    deconv_gemm<32,2><<<g, 256>>>(x,  w0,  b0,  bufA,
                                  8,8,8,128,  16,16,16,128, 2, 0);
  }
  // L2: deconv0_0, stride 1 + relu: bufA -> bufB(16^3,128)
  {
    dim3 g(4096/32, 128/64, 1);
    deconv_gemm<32,2><<<g, 256>>>(bufA, w00, b00, bufB,
                                  16,16,16,128, 16,16,16,128, 1, 1);
  }
  // L3: deconv1, stride 2: bufB -> bufA(32^3,128)
  {
    dim3 g(4096/128, 128/64, 8);
    deconv_gemm<128,8><<<g, 256>>>(bufB, w1, b1, bufA,
                                   16,16,16,128, 32,32,32,128, 2, 0);
  }
  // L4: deconv1_0, stride 1 + relu: bufA -> bufB(32^3,128)
  {
    dim3 g(32768/128, 128/64, 1);
    deconv_gemm<128,8><<<g, 256>>>(bufA, w10, b10, bufB,
                                   32,32,32,128, 32,32,32,128, 1, 1);
  }
  // L5: deconv2, stride 2: bufB -> bufA(64^3,64)
  {
    dim3 g(32768/128, 64/64, 8);
    deconv_gemm<128,8><<<g, 256>>>(bufB, w2, b2, bufA,
                                   32,32,32,128, 64,64,64,64, 2, 0);
  }
  // L6: deconv2_0, stride 1, 64->3: bufA -> out(64^3,3)
  deconv_last<<<4096, 256>>>(bufA, w20, b20, out);
}

// round 3
// speedup vs baseline: 1.0558x; 1.0558x over previous
#include <cuda_runtime.h>

// ---------------------------------------------------------------------------
// Static scratch (no allocation allowed)
// ---------------------------------------------------------------------------
__device__ float g_bufA[16777216];
__device__ float g_bufB[4194304];

// ---------------------------------------------------------------------------
// f32x2 packed helpers (fma.rn.f32x2: 2 fp32 FMAs per issue slot)
// ---------------------------------------------------------------------------
__device__ __forceinline__ unsigned long long pack2(float x, float y){
  unsigned long long r;
  asm("mov.b64 %0, {%1, %2};" : "=l"(r) : "f"(x), "f"(y));
  return r;
}
__device__ __forceinline__ void unpack2(unsigned long long v, float& x, float& y){
  asm("mov.b64 {%0, %1}, %2;" : "=f"(x), "=f"(y) : "l"(v));
}
__device__ __forceinline__ void ffma2(unsigned long long& acc,
                                      unsigned long long a, unsigned long long b){
  asm("fma.rn.f32x2 %0, %1, %2, %0;" : "+l"(acc) : "l"(a), "l"(b));
}

// ---------------------------------------------------------------------------
// ROUND-1 PROVEN KERNEL (verbatim): generic transposed-conv implicit GEMM.
// ---------------------------------------------------------------------------
template<int BM, int TM>
__global__ __launch_bounds__(256) void deconv_gemm(
    const float* __restrict__ x, const float* __restrict__ w,
    const float* __restrict__ bias, float* __restrict__ out,
    int inD, int inH, int inW, int Cin,
    int outD, int outH, int outW, int Cout,
    int stride, int relu)
{
  constexpr int BN = 64;
  constexpr int BK = 16;
  constexpr int NP = TM / 2;   // voxel pairs per thread

  __shared__ float As[BK][BM];
  __shared__ float Bs[BK][BN];
  __shared__ int   offs[BM];

  const int tid = threadIdx.x;
  const int pz = blockIdx.z;
  const int pd = (pz >> 2) & 1, ph = (pz >> 1) & 1, pw = pz & 1;
  const int rD = outD / stride, rH = outH / stride, rW = outW / stride;
  (void)rD;
  const int nb = blockIdx.y * BN;
  const int vbase = blockIdx.x * BM;

  int md = 0, mh = 0, mw = 0;
  if (tid < BM) {
    int rv = vbase + tid;
    mw = rv % rW; int t = rv / rW; mh = t % rH; md = t / rH;
  }

  int nkd, kdL[3], ddL[3];
  int nkh, khL[3], dhL[3];
  int nkw, kwL[3], dwL[3];
  auto mk = [&](int p, int& n, int* kL, int* dL){
    if (stride == 1){ n = 3; kL[0]=0; kL[1]=1; kL[2]=2; dL[0]=-1; dL[1]=0; dL[2]=1; }
    else if (p == 0){ n = 2; kL[0]=0; kL[1]=2; dL[0]=-1; dL[1]=0; }
    else            { n = 1; kL[0]=1; dL[0]=0; }
  };
  mk(pd, nkd, kdL, ddL);
  mk(ph, nkh, khL, dhL);
  mk(pw, nkw, kwL, dwL);

  const int mg = tid >> 4, ng = tid & 15;
  const int m0 = mg * TM, n0 = ng * 4;

  unsigned long long acc[NP][4];
  #pragma unroll
  for (int i = 0; i < NP; i++)
    #pragma unroll
    for (int j = 0; j < 4; j++) acc[i][j] = 0ull;

  for (int ia = 0; ia < nkd; ia++)
  for (int ib = 0; ib < nkh; ib++)
  for (int ic = 0; ic < nkw; ic++){
    const int tap = (kdL[ia]*3 + khL[ib])*3 + kwL[ic];
    const float* wt = w + (size_t)tap * Cin * Cout + nb;

    __syncthreads();
    if (tid < BM){
      int id = md + ddL[ia];
      int ih = mh + dhL[ib];
      int iw = mw + dwL[ic];
      bool v = (unsigned)id < (unsigned)inD &&
               (unsigned)ih < (unsigned)inH &&
               (unsigned)iw < (unsigned)inW;
      offs[tid] = v ? ((id*inH + ih)*inW + iw) * Cin : -1;
    }

    for (int c0 = 0; c0 < Cin; c0 += BK){
      __syncthreads();
      for (int idx = tid; idx < BM*4; idx += 256){
        int v = idx >> 2, c4 = (idx & 3) * 4;
        int o = offs[v];
        float4 val = make_float4(0.f, 0.f, 0.f, 0.f);
        if (o >= 0) val = *(const float4*)(x + o + c0 + c4);
        As[c4+0][v] = val.x; As[c4+1][v] = val.y;
        As[c4+2][v] = val.z; As[c4+3][v] = val.w;
      }
      {
        int r = tid >> 4, col = (tid & 15) * 4;
        float4 bv = *(const float4*)(wt + (size_t)(c0 + r) * Cout + col);
        *(float4*)&Bs[r][col] = bv;
      }
      __syncthreads();
      #pragma unroll
      for (int kk = 0; kk < BK; kk++){
        const unsigned long long* a64 = (const unsigned long long*)&As[kk][m0];
        float4 bv = *(const float4*)&Bs[kk][n0];
        unsigned long long bp0 = pack2(bv.x, bv.x);
        unsigned long long bp1 = pack2(bv.y, bv.y);
        unsigned long long bp2 = pack2(bv.z, bv.z);
        unsigned long long bp3 = pack2(bv.w, bv.w);
        #pragma unroll
        for (int i = 0; i < NP; i++){
          unsigned long long av = a64[i];
          ffma2(acc[i][0], av, bp0);
          ffma2(acc[i][1], av, bp1);
          ffma2(acc[i][2], av, bp2);
          ffma2(acc[i][3], av, bp3);
        }
      }
    }
  }

  float4 b4 = *(const float4*)&bias[nb + n0];
  #pragma unroll
  for (int i = 0; i < NP; i++){
    float r0[4], r1[4];
    #pragma unroll
    for (int j = 0; j < 4; j++) unpack2(acc[i][j], r0[j], r1[j]);
    #pragma unroll
    for (int h = 0; h < 2; h++){
      float* rr = h ? r1 : r0;
      int rv = vbase + m0 + 2*i + h;
      int vw = rv % rW; int t = rv / rW; int vh = t % rH; int vd = t / rH;
      int od = vd*stride + pd, oh = vh*stride + ph, ow = vw*stride + pw;
      size_t oo = (size_t)((od*outH + oh)*outW + ow) * Cout + nb + n0;
      float4 res;
      res.x = rr[0] + b4.x; res.y = rr[1] + b4.y;
      res.z = rr[2] + b4.z; res.w = rr[3] + b4.w;
      if (relu){
        res.x = fmaxf(res.x, 0.f); res.y = fmaxf(res.y, 0.f);
        res.z = fmaxf(res.z, 0.f); res.w = fmaxf(res.w, 0.f);
      }
      *(float4*)&out[oo] = res;
    }
  }
}

// ---------------------------------------------------------------------------
// NEW (round 3): specialized stride-1, Cin=Cout=128, pad 1, ReLU, DIM^3 grid.
// 8 voxel x 8 cout thread tile; B read as strided cout-pairs (conflict-free
// LDS.64); A read as LDS.128 (warp-broadcast). Linear output (no scatter).
// ---------------------------------------------------------------------------
template<int DIM>
__global__ __launch_bounds__(256) void deconv_s1r(
    const float* __restrict__ x, const float* __restrict__ w,
    const float* __restrict__ bias, float* __restrict__ out)
{
  constexpr int C  = 128;
  constexpr int BM = 128;
  constexpr int BK = 16;

  __shared__ float As[BK][BM];
  __shared__ float Bs[BK][C];
  __shared__ int   offs[BM];

  const int tid = threadIdx.x;
  const int vbase = blockIdx.x * BM;
  const int mg = tid >> 4;          // 0..15
  const int ng = tid & 15;          // 0..15
  const int m0 = mg * 8;

  // voxel coords (only threads < BM write offs)
  int md, mh, mw;
  {
    int rv = vbase + (tid & (BM-1));
    mw = rv & (DIM-1); int t = rv / DIM; mh = t & (DIM-1); md = t / DIM;
  }

  unsigned long long acc[4][8];
  #pragma unroll
  for (int i = 0; i < 4; i++)
    #pragma unroll
    for (int j = 0; j < 8; j++) acc[i][j] = 0ull;

  for (int tap = 0; tap < 27; tap++){
    const int kw = tap % 3, kh = (tap / 3) % 3, kd = tap / 9;
    const float* wt = w + tap * C * C;

    __syncthreads();                       // prior readers of offs/As done
    if (tid < BM){
      int id = md + kd - 1, ih = mh + kh - 1, iw = mw + kw - 1;
      bool v = (unsigned)id < (unsigned)DIM &&
               (unsigned)ih < (unsigned)DIM &&
               (unsigned)iw < (unsigned)DIM;
      offs[tid] = v ? ((id*DIM + ih)*DIM + iw) * C : -1;
    }

    for (int c0 = 0; c0 < C; c0 += BK){
      __syncthreads();                     // offs visible; prev tile consumed
      // A tile: 128 voxels x 16 cins (transposed)
      #pragma unroll
      for (int idx = tid; idx < BM*4; idx += 256){
        int v = idx >> 2, q = idx & 3;
        int o = offs[v];
        float4 val = make_float4(0.f, 0.f, 0.f, 0.f);
        if (o >= 0) val = *(const float4*)(x + o + c0 + q*4);
        As[q*4+0][v] = val.x; As[q*4+1][v] = val.y;
        As[q*4+2][v] = val.z; As[q*4+3][v] = val.w;
      }
      // B tile: 16 cins x 128 couts
      #pragma unroll
      for (int idx = tid; idx < BK*(C/4); idx += 256){
        int r = idx >> 5, c4 = (idx & 31) * 4;
        *(float4*)&Bs[r][c4] = *(const float4*)(wt + (c0 + r)*C + c4);
      }
      __syncthreads();
      // inner product: 32 FFMA2 per k-step
      #pragma unroll
      for (int kk = 0; kk < BK; kk++){
        float4 a0 = *(const float4*)&As[kk][m0];
        float4 a1 = *(const float4*)&As[kk][m0 + 4];
        unsigned long long av[4];
        av[0] = pack2(a0.x, a0.y); av[1] = pack2(a0.z, a0.w);
        av[2] = pack2(a1.x, a1.y); av[3] = pack2(a1.z, a1.w);
        #pragma unroll
        for (int j = 0; j < 4; j++){
          float2 bv = *(const float2*)&Bs[kk][2*(ng + j*16)];
          unsigned long long b0 = pack2(bv.x, bv.x);
          unsigned long long b1 = pack2(bv.y, bv.y);
          #pragma unroll
          for (int i = 0; i < 4; i++){
            ffma2(acc[i][2*j+0], av[i], b0);
            ffma2(acc[i][2*j+1], av[i], b1);
          }
        }
      }
    }
  }

  // epilogue: bias + relu; stride-1 output is linear in rv
  float2 bb[4];
  #pragma unroll
  for (int j = 0; j < 4; j++)
    bb[j] = *(const float2*)&bias[2*(ng + j*16)];

  #pragma unroll
  for (int i = 0; i < 4; i++){
    float v0[8], v1[8];
    #pragma unroll
    for (int t = 0; t < 8; t++) unpack2(acc[i][t], v0[t], v1[t]);
    #pragma unroll
    for (int h = 0; h < 2; h++){
      float* vv = h ? v1 : v0;
      size_t oo = (size_t)(vbase + m0 + 2*i + h) * C;
      #pragma unroll
      for (int j = 0; j < 4; j++){
        float2 r;
        r.x = fmaxf(vv[2*j+0] + bb[j].x, 0.f);
        r.y = fmaxf(vv[2*j+1] + bb[j].y, 0.f);
        *(float2*)&out[oo + 2*(ng + j*16)] = r;
      }
    }
  }
}

// ---------------------------------------------------------------------------
// ROUND-1 PROVEN KERNEL (verbatim): final layer 64^3, 64 -> 3.
// ---------------------------------------------------------------------------
__global__ __launch_bounds__(256) void deconv_last(
    const float* __restrict__ x, const float* __restrict__ w,
    const float* __restrict__ bias, float* __restrict__ out)
{
  __shared__ float ws[5184];
  __shared__ float bs[3];
  const int tid = threadIdx.x;
  for (int i = tid; i < 5184; i += 256) ws[i] = w[i];
  if (tid < 3) bs[tid] = bias[tid];
  __syncthreads();

  const int row = blockIdx.x;          // od*64 + oh
  const int od = row >> 6, oh = row & 63;
  const int warp = tid >> 5, lane = tid & 31;
  const int w3 = lane * 3;

  for (int it = 0; it < 8; ++it){
    const int ow = warp * 8 + it;
    float a0 = 0.f, a1 = 0.f, a2 = 0.f;
    #pragma unroll
    for (int kd = 0; kd < 3; kd++){
      int id = od + kd - 1;
      if ((unsigned)id >= 64u) continue;
      #pragma unroll
      for (int kh = 0; kh < 3; kh++){
        int ih = oh + kh - 1;
        if ((unsigned)ih >= 64u) continue;
        const float* xr = x + (size_t)((id*64 + ih)*64) * 64;
        const float* wr = ws + (kd*3 + kh) * 3 * 192;
        #pragma unroll
        for (int kw = 0; kw < 3; kw++){
          int iw = ow + kw - 1;
          if ((unsigned)iw >= 64u) continue;
          const float* xp = xr + iw * 64;
          float x0 = xp[lane], x1 = xp[lane + 32];
          const float* wp = wr + kw * 192;
          a0 += x0 * wp[w3+0] + x1 * wp[w3+96];
          a1 += x0 * wp[w3+1] + x1 * wp[w3+97];
          a2 += x0 * wp[w3+2] + x1 * wp[w3+98];
        }
      }
    }
    #pragma unroll
    for (int s = 16; s > 0; s >>= 1){
      a0 += __shfl_xor_sync(0xffffffffu, a0, s);
      a1 += __shfl_xor_sync(0xffffffffu, a1, s);
      a2 += __shfl_xor_sync(0xffffffffu, a2, s);
    }
    if (lane == 0){
      float* op = out + ((size_t)row * 64 + ow) * 3;
      op[0] = a0 + bs[0];
      op[1] = a1 + bs[1];
      op[2] = a2 + bs[2];
    }
  }
}

// ---------------------------------------------------------------------------
// kernel_launch: round-1 launches everywhere except L4 (new deconv_s1r<32>).
// ---------------------------------------------------------------------------
extern "C" void kernel_launch(void* const* d_in, const int* in_sizes, int n_in,
                              void* d_out, int out_size)
{
  (void)in_sizes; (void)n_in; (void)out_size;
  const float* x   = (const float*)d_in[0];
  const float* w0  = (const float*)d_in[1];
  const float* b0  = (const float*)d_in[2];
  const float* w00 = (const float*)d_in[3];
  const float* b00 = (const float*)d_in[4];
  const float* w1  = (const float*)d_in[5];
  const float* b1  = (const float*)d_in[6];
  const float* w10 = (const float*)d_in[7];
  const float* b10 = (const float*)d_in[8];
  const float* w2  = (const float*)d_in[9];
  const float* b2  = (const float*)d_in[10];
  const float* w20 = (const float*)d_in[11];
  const float* b20 = (const float*)d_in[12];
  float* out = (float*)d_out;

  float *bufA = nullptr, *bufB = nullptr;
  cudaGetSymbolAddress((void**)&bufA, g_bufA);
  cudaGetSymbolAddress((void**)&bufB, g_bufB);

  // L1: deconv0 s2: x(8^3,128) -> bufA(16^3,128)
  {
    dim3 g(512/32, 128/64, 8);
    deconv_gemm<32,2><<<g, 256>>>(x,  w0,  b0,  bufA,
                                  8,8,8,128,  16,16,16,128, 2, 0);
  }
  // L2: deconv0_0 s1 + relu: bufA -> bufB(16^3,128)
  {
    dim3 g(4096/32, 128/64, 1);
    deconv_gemm<32,2><<<g, 256>>>(bufA, w00, b00, bufB,
                                  16,16,16,128, 16,16,16,128, 1, 1);
  }
  // L3: deconv1 s2: bufB -> bufA(32^3,128)
  {
    dim3 g(4096/128, 128/64, 8);
    deconv_gemm<128,8><<<g, 256>>>(bufB, w1, b1, bufA,
                                   16,16,16,128, 32,32,32,128, 2, 0);
  }
  // L4: deconv1_0 s1 + relu: bufA -> bufB(32^3,128)   [NEW kernel]
  deconv_s1r<32><<<32768/128, 256>>>(bufA, w10, b10, bufB);

  // L5: deconv2 s2: bufB -> bufA(64^3,64)
  {
    dim3 g(32768/128, 64/64, 8);
    deconv_gemm<128,8><<<g, 256>>>(bufB, w2, b2, bufA,
                                   32,32,32,128, 64,64,64,64, 2, 0);
  }
  // L6: deconv2_0 s1, 64->3: bufA -> out(64^3,3)
  deconv_last<<<4096, 256>>>(bufA, w20, b20, out);
}